// round 1
// baseline (speedup 1.0000x reference)
#include <cuda_runtime.h>

#define NLAYERS 32
#define ROWS_PER_THREAD 8
#define CLIPV 5.0f

__device__ __forceinline__ float clip5(float v) {
    return fminf(fmaxf(v, -CLIPV), CLIPV);
}

// tanh(x) = 1 - 2/(exp(2x)+1), via MUFU.EX2 + MUFU.RCP.
// Abs error ~1e-6; saturates correctly to +/-1 for large |x| (rcp(inf)=0).
__device__ __forceinline__ float fast_tanh(float x) {
    float p = x * 2.8853900817779268f;   // 2 * log2(e)
    float e;
    asm("ex2.approx.f32 %0, %1;" : "=f"(e) : "f"(p));
    float d = e + 1.0f;
    float r;
    asm("rcp.approx.f32 %0, %1;" : "=f"(r) : "f"(d));
    return fmaf(-2.0f, r, 1.0f);
}

__global__ void __launch_bounds__(256) fraud_kernel(
    const float* __restrict__ x,      // [B,2]
    const float* __restrict__ W,      // [32,2,2]
    const float* __restrict__ b,      // [32,2]
    const float* __restrict__ scale,  // [32,2]
    const float* __restrict__ shift,  // [32,2]
    const float* __restrict__ Wo,     // [1,2]
    const float* __restrict__ bo,     // [1]
    float* __restrict__ out,          // [B,1]
    int nrows)
{
    __shared__ float4 sW[NLAYERS];   // w00,w01,w10,w11
    __shared__ float4 sB[NLAYERS];   // b0,b1,s0,s1
    __shared__ float2 sS[NLAYERS];   // sh0,sh1
    __shared__ float  sO[3];         // wo0,wo1,b_out

    const int t = threadIdx.x;
    if (t < NLAYERS) {
        float4 w = reinterpret_cast<const float4*>(W)[t];
        float b0v = b[2 * t], b1v = b[2 * t + 1];
        if (t > 0) {  // layers 1..31 clipped at construction; layer 0 not
            w.x = clip5(w.x); w.y = clip5(w.y);
            w.z = clip5(w.z); w.w = clip5(w.w);
            b0v = clip5(b0v); b1v = clip5(b1v);
        }
        sW[t] = w;
        sB[t] = make_float4(b0v, b1v, scale[2 * t], scale[2 * t + 1]);
        sS[t] = make_float2(shift[2 * t], shift[2 * t + 1]);
    }
    if (t == 0) { sO[0] = Wo[0]; sO[1] = Wo[1]; sO[2] = bo[0]; }
    __syncthreads();

    const long base = (long)(blockIdx.x * (long)blockDim.x + threadIdx.x) * ROWS_PER_THREAD;
    if (base >= nrows) return;

    float h0[ROWS_PER_THREAD];
    float h1[ROWS_PER_THREAD];

    const bool full = (base + ROWS_PER_THREAD) <= (long)nrows;

    if (full) {
        // 4 x LDG.128, 32B contiguous per thread -> coalesced
        const float4* xin = reinterpret_cast<const float4*>(x) + (base >> 1);
        #pragma unroll
        for (int i = 0; i < ROWS_PER_THREAD / 2; i++) {
            float4 v = xin[i];
            h0[2 * i]     = v.x; h1[2 * i]     = v.y;
            h0[2 * i + 1] = v.z; h1[2 * i + 1] = v.w;
        }
    } else {
        #pragma unroll
        for (int r = 0; r < ROWS_PER_THREAD; r++) {
            long row = base + r;
            if (row < nrows) { h0[r] = x[2 * row]; h1[r] = x[2 * row + 1]; }
            else             { h0[r] = 0.0f;       h1[r] = 0.0f; }
        }
    }

    // Keep the layer loop rolled: body stays in L0 I-cache; rows unrolled for ILP
    #pragma unroll 1
    for (int l = 0; l < NLAYERS; l++) {
        const float4 w  = sW[l];
        const float4 bs = sB[l];
        const float2 sh = sS[l];
        #pragma unroll
        for (int r = 0; r < ROWS_PER_THREAD; r++) {
            float a0 = fmaf(w.x, h0[r], fmaf(w.y, h1[r], bs.x));
            float a1 = fmaf(w.z, h0[r], fmaf(w.w, h1[r], bs.y));
            h0[r] = fmaf(fast_tanh(a0), bs.z, sh.x);
            h1[r] = fmaf(fast_tanh(a1), bs.w, sh.y);
        }
    }

    const float wo0 = sO[0], wo1 = sO[1], bov = sO[2];

    if (full) {
        float4* op = reinterpret_cast<float4*>(out + base);
        #pragma unroll
        for (int i = 0; i < ROWS_PER_THREAD / 4; i++) {
            float4 v;
            v.x = fmaf(h0[4 * i + 0], wo0, fmaf(h1[4 * i + 0], wo1, bov));
            v.y = fmaf(h0[4 * i + 1], wo0, fmaf(h1[4 * i + 1], wo1, bov));
            v.z = fmaf(h0[4 * i + 2], wo0, fmaf(h1[4 * i + 2], wo1, bov));
            v.w = fmaf(h0[4 * i + 3], wo0, fmaf(h1[4 * i + 3], wo1, bov));
            op[i] = v;
        }
    } else {
        #pragma unroll
        for (int r = 0; r < ROWS_PER_THREAD; r++) {
            long row = base + r;
            if (row < nrows)
                out[row] = fmaf(h0[r], wo0, fmaf(h1[r], wo1, bov));
        }
    }
}

extern "C" void kernel_launch(void* const* d_in, const int* in_sizes, int n_in,
                              void* d_out, int out_size) {
    const float* x     = (const float*)d_in[0];
    const float* W     = (const float*)d_in[1];
    const float* b     = (const float*)d_in[2];
    const float* scale = (const float*)d_in[3];
    const float* shift = (const float*)d_in[4];
    const float* Wo    = (const float*)d_in[5];
    const float* bo    = (const float*)d_in[6];
    float* out = (float*)d_out;

    const int nrows = in_sizes[0] / 2;
    const int threads = 256;
    const long total_threads = (nrows + ROWS_PER_THREAD - 1) / ROWS_PER_THREAD;
    const int blocks = (int)((total_threads + threads - 1) / threads);

    fraud_kernel<<<blocks, threads>>>(x, W, b, scale, shift, Wo, bo, out, nrows);
}

// round 2
// speedup vs baseline: 1.1615x; 1.1615x over previous
#include <cuda_runtime.h>

#define NLAYERS 32
#define ROWS_PER_THREAD 8
#define CLIPV 5.0f

__device__ __forceinline__ float clip5(float v) {
    return fminf(fmaxf(v, -CLIPV), CLIPV);
}

// Single-instruction MUFU.TANH (sm_75+). 1 MUFU op per tanh instead of the
// 2 (EX2+RCP) + 3 fma-pipe ops of the exp-based formulation. Abs error
// ~1e-4..5e-4 per op; the network contracts per-op error (round-0: 1e-6
// per-op -> 9.6e-8 final), so final rel_err stays well under 1e-3.
__device__ __forceinline__ float fast_tanh(float x) {
    float r;
    asm("tanh.approx.f32 %0, %1;" : "=f"(r) : "f"(x));
    return r;
}

__global__ void __launch_bounds__(256) fraud_kernel(
    const float* __restrict__ x,      // [B,2]
    const float* __restrict__ W,      // [32,2,2]
    const float* __restrict__ b,      // [32,2]
    const float* __restrict__ scale,  // [32,2]
    const float* __restrict__ shift,  // [32,2]
    const float* __restrict__ Wo,     // [1,2]
    const float* __restrict__ bo,     // [1]
    float* __restrict__ out,          // [B,1]
    int nrows)
{
    __shared__ float4 sW[NLAYERS];   // w00,w01,w10,w11
    __shared__ float4 sB[NLAYERS];   // b0,b1,s0,s1
    __shared__ float2 sS[NLAYERS];   // sh0,sh1
    __shared__ float  sO[3];         // wo0,wo1,b_out

    const int t = threadIdx.x;
    if (t < NLAYERS) {
        float4 w = reinterpret_cast<const float4*>(W)[t];
        float b0v = b[2 * t], b1v = b[2 * t + 1];
        if (t > 0) {  // layers 1..31 clipped at construction; layer 0 not
            w.x = clip5(w.x); w.y = clip5(w.y);
            w.z = clip5(w.z); w.w = clip5(w.w);
            b0v = clip5(b0v); b1v = clip5(b1v);
        }
        sW[t] = w;
        sB[t] = make_float4(b0v, b1v, scale[2 * t], scale[2 * t + 1]);
        sS[t] = make_float2(shift[2 * t], shift[2 * t + 1]);
    }
    if (t == 0) { sO[0] = Wo[0]; sO[1] = Wo[1]; sO[2] = bo[0]; }
    __syncthreads();

    const long base = (long)(blockIdx.x * (long)blockDim.x + threadIdx.x) * ROWS_PER_THREAD;
    if (base >= nrows) return;

    float h0[ROWS_PER_THREAD];
    float h1[ROWS_PER_THREAD];

    const bool full = (base + ROWS_PER_THREAD) <= (long)nrows;

    if (full) {
        // 4 x LDG.128, 32B contiguous per thread -> coalesced
        const float4* xin = reinterpret_cast<const float4*>(x) + (base >> 1);
        #pragma unroll
        for (int i = 0; i < ROWS_PER_THREAD / 2; i++) {
            float4 v = xin[i];
            h0[2 * i]     = v.x; h1[2 * i]     = v.y;
            h0[2 * i + 1] = v.z; h1[2 * i + 1] = v.w;
        }
    } else {
        #pragma unroll
        for (int r = 0; r < ROWS_PER_THREAD; r++) {
            long row = base + r;
            if (row < nrows) { h0[r] = x[2 * row]; h1[r] = x[2 * row + 1]; }
            else             { h0[r] = 0.0f;       h1[r] = 0.0f; }
        }
    }

    // Layer loop rolled (L0 I-cache); rows unrolled for MUFU-latency-hiding ILP
    #pragma unroll 1
    for (int l = 0; l < NLAYERS; l++) {
        const float4 w  = sW[l];
        const float4 bs = sB[l];
        const float2 sh = sS[l];
        #pragma unroll
        for (int r = 0; r < ROWS_PER_THREAD; r++) {
            float a0 = fmaf(w.x, h0[r], fmaf(w.y, h1[r], bs.x));
            float a1 = fmaf(w.z, h0[r], fmaf(w.w, h1[r], bs.y));
            h0[r] = fmaf(fast_tanh(a0), bs.z, sh.x);
            h1[r] = fmaf(fast_tanh(a1), bs.w, sh.y);
        }
    }

    const float wo0 = sO[0], wo1 = sO[1], bov = sO[2];

    if (full) {
        float4* op = reinterpret_cast<float4*>(out + base);
        #pragma unroll
        for (int i = 0; i < ROWS_PER_THREAD / 4; i++) {
            float4 v;
            v.x = fmaf(h0[4 * i + 0], wo0, fmaf(h1[4 * i + 0], wo1, bov));
            v.y = fmaf(h0[4 * i + 1], wo0, fmaf(h1[4 * i + 1], wo1, bov));
            v.z = fmaf(h0[4 * i + 2], wo0, fmaf(h1[4 * i + 2], wo1, bov));
            v.w = fmaf(h0[4 * i + 3], wo0, fmaf(h1[4 * i + 3], wo1, bov));
            op[i] = v;
        }
    } else {
        #pragma unroll
        for (int r = 0; r < ROWS_PER_THREAD; r++) {
            long row = base + r;
            if (row < nrows)
                out[row] = fmaf(h0[r], wo0, fmaf(h1[r], wo1, bov));
        }
    }
}

extern "C" void kernel_launch(void* const* d_in, const int* in_sizes, int n_in,
                              void* d_out, int out_size) {
    const float* x     = (const float*)d_in[0];
    const float* W     = (const float*)d_in[1];
    const float* b     = (const float*)d_in[2];
    const float* scale = (const float*)d_in[3];
    const float* shift = (const float*)d_in[4];
    const float* Wo    = (const float*)d_in[5];
    const float* bo    = (const float*)d_in[6];
    float* out = (float*)d_out;

    const int nrows = in_sizes[0] / 2;
    const int threads = 256;
    const long total_threads = (nrows + ROWS_PER_THREAD - 1) / ROWS_PER_THREAD;
    const int blocks = (int)((total_threads + threads - 1) / threads);

    fraud_kernel<<<blocks, threads>>>(x, W, b, scale, shift, Wo, bo, out, nrows);
}

// round 3
// speedup vs baseline: 2.0633x; 1.7765x over previous
#include <cuda_runtime.h>

#define NLAYERS 32
#define RPT 8               // rows per thread
#define NPAIR (RPT / 2)
#define CLIPV 5.0f

__device__ __forceinline__ float clip5(float v) {
    return fminf(fmaxf(v, -CLIPV), CLIPV);
}

__device__ __forceinline__ float fast_tanh(float x) {
    float r;
    asm("tanh.approx.f32 %0, %1;" : "=f"(r) : "f"(x));
    return r;
}

// ---- packed f32x2 helpers (Blackwell): two fp32 lanes per instruction ----
typedef unsigned long long u64;

__device__ __forceinline__ u64 pack2(float lo, float hi) {
    u64 r;
    asm("mov.b64 %0, {%1, %2};" : "=l"(r) : "f"(lo), "f"(hi));
    return r;
}
__device__ __forceinline__ float lo2(u64 v) { return __uint_as_float((unsigned)v); }
__device__ __forceinline__ float hi2(u64 v) { return __uint_as_float((unsigned)(v >> 32)); }

__device__ __forceinline__ u64 ffma2(u64 a, u64 b, u64 c) {
    u64 r;
    asm("fma.rn.f32x2 %0, %1, %2, %3;" : "=l"(r) : "l"(a), "l"(b), "l"(c));
    return r;
}
__device__ __forceinline__ u64 bcast2(float v) { return pack2(v, v); }

__global__ void __launch_bounds__(256) fraud_kernel(
    const float* __restrict__ x,      // [B,2]
    const float* __restrict__ W,      // [32,2,2]
    const float* __restrict__ b,      // [32,2]
    const float* __restrict__ scale,  // [32,2]
    const float* __restrict__ shift,  // [32,2]
    const float* __restrict__ Wo,     // [1,2]
    const float* __restrict__ bo,     // [1]
    float* __restrict__ out,          // [B,1]
    int nrows)
{
    // Fused params: for l in [0,31):  a_{l+1} = M_l * tanh(a_l) + c_l
    //   M_l = clip(W_{l+1}) * diag(scale_l)
    //   c_l = clip(W_{l+1}) @ shift_l + clip(b_{l+1})
    // Head: out = (Wo*s_31) . tanh(a_31) + (Wo . sh_31 + bo)
    __shared__ float4 sM[NLAYERS - 1];
    __shared__ float2 sC[NLAYERS - 1];
    __shared__ float4 sW0;            // layer 0 weights (unclipped)
    __shared__ float2 sB0;
    __shared__ float  sF[3];          // v0, v1, c_out

    const int t = threadIdx.x;
    if (t < NLAYERS - 1) {
        float4 w = reinterpret_cast<const float4*>(W)[t + 1];
        w.x = clip5(w.x); w.y = clip5(w.y); w.z = clip5(w.z); w.w = clip5(w.w);
        float bb0 = clip5(b[2 * (t + 1)]);
        float bb1 = clip5(b[2 * (t + 1) + 1]);
        float s0 = scale[2 * t], s1 = scale[2 * t + 1];
        float h0 = shift[2 * t], h1 = shift[2 * t + 1];
        sM[t] = make_float4(w.x * s0, w.y * s1, w.z * s0, w.w * s1);
        sC[t] = make_float2(fmaf(w.x, h0, fmaf(w.y, h1, bb0)),
                            fmaf(w.z, h0, fmaf(w.w, h1, bb1)));
    } else if (t == NLAYERS - 1) {
        float s0 = scale[2 * 31], s1 = scale[2 * 31 + 1];
        float h0 = shift[2 * 31], h1 = shift[2 * 31 + 1];
        sF[0] = Wo[0] * s0;
        sF[1] = Wo[1] * s1;
        sF[2] = fmaf(Wo[0], h0, fmaf(Wo[1], h1, bo[0]));
    } else if (t == NLAYERS) {
        sW0 = reinterpret_cast<const float4*>(W)[0];   // layer 0: no clip
        sB0 = make_float2(b[0], b[1]);
    }
    __syncthreads();

    const long base = (long)(blockIdx.x * (long)blockDim.x + threadIdx.x) * RPT;
    if (base >= nrows) return;

    const bool full = (base + RPT) <= (long)nrows;

    u64 a0[NPAIR], a1[NPAIR];   // pre-activations, rows paired (2p, 2p+1)

    {
        const float4 w0 = sW0;
        const float2 b0 = sB0;
        const u64 W00 = bcast2(w0.x), W01 = bcast2(w0.y);
        const u64 W10 = bcast2(w0.z), W11 = bcast2(w0.w);
        const u64 B0 = bcast2(b0.x), B1 = bcast2(b0.y);

        if (full) {
            const float4* xin = reinterpret_cast<const float4*>(x) + (base >> 1);
            #pragma unroll
            for (int p = 0; p < NPAIR; p++) {
                float4 v = xin[p];                 // rows 2p:(v.x,v.y), 2p+1:(v.z,v.w)
                u64 x0 = pack2(v.x, v.z);
                u64 x1 = pack2(v.y, v.w);
                a0[p] = ffma2(W00, x0, ffma2(W01, x1, B0));
                a1[p] = ffma2(W10, x0, ffma2(W11, x1, B1));
            }
        } else {
            #pragma unroll
            for (int p = 0; p < NPAIR; p++) {
                float x0a = 0.f, x1a = 0.f, x0b = 0.f, x1b = 0.f;
                long ra = base + 2 * p, rb = ra + 1;
                if (ra < nrows) { x0a = x[2 * ra]; x1a = x[2 * ra + 1]; }
                if (rb < nrows) { x0b = x[2 * rb]; x1b = x[2 * rb + 1]; }
                u64 x0 = pack2(x0a, x0b);
                u64 x1 = pack2(x1a, x1b);
                a0[p] = ffma2(W00, x0, ffma2(W01, x1, B0));
                a1[p] = ffma2(W10, x0, ffma2(W11, x1, B1));
            }
        }
    }

    // 31 fused layers: tanh then next linear. Loop rolled for L0 I-cache.
    #pragma unroll 1
    for (int l = 0; l < NLAYERS - 1; l++) {
        const float4 M = sM[l];
        const float2 C = sC[l];
        const u64 M00 = bcast2(M.x), M01 = bcast2(M.y);
        const u64 M10 = bcast2(M.z), M11 = bcast2(M.w);
        const u64 C0 = bcast2(C.x), C1 = bcast2(C.y);
        #pragma unroll
        for (int p = 0; p < NPAIR; p++) {
            u64 t0 = pack2(fast_tanh(lo2(a0[p])), fast_tanh(hi2(a0[p])));
            u64 t1 = pack2(fast_tanh(lo2(a1[p])), fast_tanh(hi2(a1[p])));
            a0[p] = ffma2(M00, t0, ffma2(M01, t1, C0));
            a1[p] = ffma2(M10, t0, ffma2(M11, t1, C1));
        }
    }

    // Final tanh + folded output head
    const u64 V0 = bcast2(sF[0]);
    const u64 V1 = bcast2(sF[1]);
    const u64 CO = bcast2(sF[2]);

    u64 o[NPAIR];
    #pragma unroll
    for (int p = 0; p < NPAIR; p++) {
        u64 t0 = pack2(fast_tanh(lo2(a0[p])), fast_tanh(hi2(a0[p])));
        u64 t1 = pack2(fast_tanh(lo2(a1[p])), fast_tanh(hi2(a1[p])));
        o[p] = ffma2(V0, t0, ffma2(V1, t1, CO));   // (out_{2p}, out_{2p+1})
    }

    if (full) {
        float4* op = reinterpret_cast<float4*>(out + base);
        #pragma unroll
        for (int i = 0; i < NPAIR / 2; i++) {
            float4 v;
            v.x = lo2(o[2 * i]);     v.y = hi2(o[2 * i]);
            v.z = lo2(o[2 * i + 1]); v.w = hi2(o[2 * i + 1]);
            op[i] = v;
        }
    } else {
        #pragma unroll
        for (int p = 0; p < NPAIR; p++) {
            long ra = base + 2 * p, rb = ra + 1;
            if (ra < nrows) out[ra] = lo2(o[p]);
            if (rb < nrows) out[rb] = hi2(o[p]);
        }
    }
}

extern "C" void kernel_launch(void* const* d_in, const int* in_sizes, int n_in,
                              void* d_out, int out_size) {
    const float* x     = (const float*)d_in[0];
    const float* W     = (const float*)d_in[1];
    const float* b     = (const float*)d_in[2];
    const float* scale = (const float*)d_in[3];
    const float* shift = (const float*)d_in[4];
    const float* Wo    = (const float*)d_in[5];
    const float* bo    = (const float*)d_in[6];
    float* out = (float*)d_out;

    const int nrows = in_sizes[0] / 2;
    const int threads = 256;
    const long total_threads = (nrows + RPT - 1) / RPT;
    const int blocks = (int)((total_threads + threads - 1) / threads);

    fraud_kernel<<<blocks, threads>>>(x, W, b, scale, shift, Wo, bo, out, nrows);
}